// round 13
// baseline (speedup 1.0000x reference)
#include <cuda_runtime.h>

// GRUExtractor: 2-layer GRU, B=4096, T=256, I=16, H=40, fp32.
// R13: U=4 gate-rows per thread (half-k) -> 8 ffma2 per broadcast LDS.128;
//      512-thread CTA (2 slots x 256, 128 regs/thr for 80-reg weight cache);
//      Phase B vectorized float2; L1 r/z biases precombined; xg prepass kept.

#define HSZ 40
#define ISZ 16
#define TSZ 256
#define NB  4096
#define NR  14
#define SLOT_T 256
#define CTA_T  512
#define NGR 120

typedef unsigned long long u64;
typedef ulonglong2 u64x2;

__device__ float g_xg[(size_t)NB * TSZ * NGR];   // xg[b][t][gate_row]

__device__ __forceinline__ void upk2(u64 d, float& a, float& b) {
    asm("mov.b64 {%0,%1},%2;" : "=f"(a), "=f"(b) : "l"(d));
}
__device__ __forceinline__ u64 ffma2(u64 a, u64 b, u64 c) {
    u64 d; asm("fma.rn.f32x2 %0,%1,%2,%3;" : "=l"(d) : "l"(a), "l"(b), "l"(c)); return d;
}
__device__ __forceinline__ u64 add2(u64 a, u64 b) {
    u64 d; asm("add.rn.f32x2 %0,%1,%2;" : "=l"(d) : "l"(a), "l"(b)); return d;
}
__device__ __forceinline__ float hsum2(u64 d) { float a, b; upk2(d, a, b); return a + b; }

__device__ __forceinline__ float sigm(float x) {
    return __fdividef(1.0f, 1.0f + __expf(-x));
}
__device__ __forceinline__ float tanh_f(float x) {
    return __fdividef(2.0f, 1.0f + __expf(-2.0f * x)) - 1.0f;
}

__device__ __forceinline__ void slot_bar(int slot) {
    asm volatile("bar.sync %0, %1;" :: "r"(slot + 1), "r"(SLOT_T) : "memory");
}

// ---------------- prepass: xg = Wih0 . x + bih0 ----------------
__global__ void __launch_bounds__(128, 8) xg_prepass(
    const float* __restrict__ x, const float* __restrict__ Wih0,
    const float* __restrict__ bih0)
{
    __shared__ __align__(16) float4 xs[TSZ * 4];
    const int b = blockIdx.x;
    const int tid = threadIdx.x;
    for (int i = tid; i < TSZ * 4; i += 128)
        xs[i] = ((const float4*)x)[b * (TSZ * 4) + i];
    u64 w[8]; float bias = 0.0f;
    const int gr = tid;
    if (gr < NGR) {
        const u64x2* wp = (const u64x2*)(Wih0 + gr * ISZ);
        #pragma unroll
        for (int q = 0; q < 4; q++) { u64x2 v = wp[q]; w[2*q] = v.x; w[2*q+1] = v.y; }
        bias = bih0[gr];
    }
    __syncthreads();
    if (gr < NGR) {
        float* dst = g_xg + (size_t)b * TSZ * NGR + gr;
        #pragma unroll 4
        for (int t = 0; t < TSZ; t++) {
            const u64x2* xp = (const u64x2*)&xs[t * 4];
            u64 a0 = 0ull, a1 = 0ull;
            #pragma unroll
            for (int q = 0; q < 4; q++) {
                u64x2 v = xp[q];
                a0 = ffma2(w[2*q],   v.x, a0);
                a1 = ffma2(w[2*q+1], v.y, a1);
            }
            dst[t * NGR] = hsum2(add2(a0, a1)) + bias;
        }
    }
}

// ---------------- main recurrent kernel ----------------
struct Slot {
    float h0[NR][HSZ];
    float h1[NR][HSZ];
    float pA[2][NR][NGR];         // L0 partials [half]
    float pB[2][2][NR][NGR];      // L1 partials [mat][half]
    float xb[2][NR][NGR];         // xg double buffer
};
struct CTAS {
    Slot sl[2];
    float b0[NGR];                // bhh0
    float cb1[80];                // bih1+bhh1 (r,z gates)
    float bi1n[40], bh1n[40];     // bih1[80+j], bhh1[80+j]
};

__global__ void __launch_bounds__(CTA_T, 1) gru_main(
    const float* __restrict__ Whh0,
    const float* __restrict__ bhh0,
    const float* __restrict__ Wih1,
    const float* __restrict__ Whh1,
    const float* __restrict__ bih1,
    const float* __restrict__ bhh1,
    float* __restrict__ out)
{
    extern __shared__ __align__(16) char smraw[];
    CTAS& C = *(CTAS*)smraw;

    const int tid  = threadIdx.x;
    const int slot = tid >> 8;
    const int r    = tid & 255;
    Slot& S = C.sl[slot];
    const int base = (blockIdx.x * 2 + slot) * NR;

    // ---- roles ----
    const bool isL0 = (r < 60);
    const bool isL1 = (r >= 64 && r < 184);
    int half = 0, mat = 0, gr0 = 0;
    const float* Wsrc = Whh0;
    if (isL0) {
        half = r & 1; gr0 = (r >> 1) * 4; Wsrc = Whh0;
    } else if (isL1) {
        int i = r - 64;
        half = i & 1; mat = (i >> 1) & 1; gr0 = (i >> 2) * 4;
        Wsrc = mat ? Whh1 : Wih1;
    }
    const int hofs = half * 20;

    // ---- register weights: 4 gate-rows x half-k = 40 u64 ----
    u64 w[40];
    if (isL0 || isL1) {
        #pragma unroll
        for (int t = 0; t < 4; t++) {
            const u64x2* p = (const u64x2*)(Wsrc + (gr0 + t) * HSZ + hofs);
            #pragma unroll
            for (int q = 0; q < 5; q++) {
                u64x2 v = p[q];
                w[t * 10 + 2 * q]     = v.x;
                w[t * 10 + 2 * q + 1] = v.y;
            }
        }
    }

    // ---- init ----
    for (int e = r; e < NR * HSZ; e += SLOT_T) {
        S.h0[e / HSZ][e % HSZ] = 0.0f;
        S.h1[e / HSZ][e % HSZ] = 0.0f;
    }
    if (tid < NGR) C.b0[tid] = bhh0[tid];
    else if (tid < NGR + 80) { int j = tid - NGR; C.cb1[j] = bih1[j] + bhh1[j]; }
    else if (tid < NGR + 120) {
        int j = tid - NGR - 80;
        C.bi1n[j] = bih1[80 + j]; C.bh1n[j] = bhh1[80 + j];
    }
    for (int idx = r; idx < NR * 30; idx += SLOT_T) {
        int row = idx / 30, c = idx - row * 30;
        int grow = base + row; if (grow > NB - 1) grow = NB - 1;
        ((float4*)S.xb[0][row])[c] =
            ((const float4*)g_xg)[((size_t)grow * TSZ) * 30 + c];
    }
    __syncthreads();

    // ---- supersteps: L0 computes t=s, L1 computes t=s-1 ----
    for (int s = 0; s <= TSZ; ++s) {
        // register prefetch of xg(s+1)
        float4 pf0, pf1;
        int pi0 = -1, pi1 = -1;
        const int s1 = s + 1;
        if (s1 < TSZ) {
            if (r < NR * 30) {
                int row = r / 30, c = r - row * 30;
                int grow = base + row; if (grow > NB - 1) grow = NB - 1;
                pf0 = ((const float4*)g_xg)[((size_t)grow * TSZ + s1) * 30 + c];
                pi0 = r;
            }
            int idx = r + SLOT_T;
            if (idx < NR * 30) {
                int row = idx / 30, c = idx - row * 30;
                int grow = base + row; if (grow > NB - 1) grow = NB - 1;
                pf1 = ((const float4*)g_xg)[((size_t)grow * TSZ + s1) * 30 + c];
                pi1 = idx;
            }
        }

        // ===== PHASE A: partial h-dots, 4 gate-rows per thread =====
        const bool act = isL0 ? (s < TSZ) : (isL1 && s >= 1);
        if (act) {
            const float (*hsrc)[HSZ] = (isL0 || mat == 0) ? S.h0 : S.h1;
            float* pout = isL0 ? &S.pA[half][0][0] : &S.pB[mat][half][0][0];
            #pragma unroll 2
            for (int row = 0; row < NR; ++row) {
                const u64x2* hp = (const u64x2*)(&hsrc[row][hofs]);
                u64x2 v0 = hp[0], v1 = hp[1], v2 = hp[2], v3 = hp[3], v4 = hp[4];
                float4 res;
                #pragma unroll
                for (int t = 0; t < 4; t++) {
                    u64 a0 = 0ull, a1 = 0ull;
                    a0 = ffma2(w[t*10+0], v0.x, a0); a1 = ffma2(w[t*10+1], v0.y, a1);
                    a0 = ffma2(w[t*10+2], v1.x, a0); a1 = ffma2(w[t*10+3], v1.y, a1);
                    a0 = ffma2(w[t*10+4], v2.x, a0); a1 = ffma2(w[t*10+5], v2.y, a1);
                    a0 = ffma2(w[t*10+6], v3.x, a0); a1 = ffma2(w[t*10+7], v3.y, a1);
                    a0 = ffma2(w[t*10+8], v4.x, a0); a1 = ffma2(w[t*10+9], v4.y, a1);
                    ((float*)&res)[t] = hsum2(add2(a0, a1));
                }
                *(float4*)&pout[row * NGR + gr0] = res;
            }
        }

        // commit xg prefetch to other parity buffer
        if (pi0 >= 0) ((float4*)&S.xb[s1 & 1][0][0])[pi0] = pf0;
        if (pi1 >= 0) ((float4*)&S.xb[s1 & 1][0][0])[pi1] = pf1;
        slot_bar(slot);

        // ===== PHASE B: combine + activations + h update, float2 (560 tasks) =====
        #pragma unroll
        for (int k = 0; k < 3; k++) {
            int t = r + SLOT_T * k;
            if (t < 2 * NR * 20) {
                int lay = t / (NR * 20);
                int rem = t - lay * (NR * 20);
                int row = rem / 20;
                int jp  = (rem - row * 20) * 2;
                if (lay == 0) {
                    if (s < TSZ) {
                        const float* q0 = S.pA[0][row];
                        const float* q1 = S.pA[1][row];
                        const float* xv = S.xb[s & 1][row];
                        float2 a, b;
                        a = *(const float2*)(q0 + jp);      b = *(const float2*)(q1 + jp);
                        float2 hr = make_float2(a.x + b.x, a.y + b.y);
                        a = *(const float2*)(q0 + 40 + jp); b = *(const float2*)(q1 + 40 + jp);
                        float2 hz = make_float2(a.x + b.x, a.y + b.y);
                        a = *(const float2*)(q0 + 80 + jp); b = *(const float2*)(q1 + 80 + jp);
                        float2 hn = make_float2(a.x + b.x, a.y + b.y);
                        float2 xr = *(const float2*)(xv + jp);
                        float2 xz = *(const float2*)(xv + 40 + jp);
                        float2 xn = *(const float2*)(xv + 80 + jp);
                        float2 br = *(const float2*)(C.b0 + jp);
                        float2 bz = *(const float2*)(C.b0 + 40 + jp);
                        float2 bn = *(const float2*)(C.b0 + 80 + jp);
                        float2 h  = *(float2*)&S.h0[row][jp];
                        float r0 = sigm(xr.x + hr.x + br.x);
                        float r1 = sigm(xr.y + hr.y + br.y);
                        float z0 = sigm(xz.x + hz.x + bz.x);
                        float z1 = sigm(xz.y + hz.y + bz.y);
                        float n0 = tanh_f(fmaf(r0, hn.x + bn.x, xn.x));
                        float n1 = tanh_f(fmaf(r1, hn.y + bn.y, xn.y));
                        h.x = fmaf(z0, h.x - n0, n0);
                        h.y = fmaf(z1, h.y - n1, n1);
                        *(float2*)&S.h0[row][jp] = h;
                    }
                } else {
                    if (s >= 1) {
                        const float* i0 = S.pB[0][0][row];
                        const float* i1 = S.pB[0][1][row];
                        const float* g0 = S.pB[1][0][row];
                        const float* g1 = S.pB[1][1][row];
                        float2 a, b;
                        a = *(const float2*)(i0 + jp);      b = *(const float2*)(i1 + jp);
                        float2 ir = make_float2(a.x + b.x, a.y + b.y);
                        a = *(const float2*)(g0 + jp);      b = *(const float2*)(g1 + jp);
                        float2 hr = make_float2(a.x + b.x, a.y + b.y);
                        a = *(const float2*)(i0 + 40 + jp); b = *(const float2*)(i1 + 40 + jp);
                        float2 iz = make_float2(a.x + b.x, a.y + b.y);
                        a = *(const float2*)(g0 + 40 + jp); b = *(const float2*)(g1 + 40 + jp);
                        float2 hz = make_float2(a.x + b.x, a.y + b.y);
                        a = *(const float2*)(i0 + 80 + jp); b = *(const float2*)(i1 + 80 + jp);
                        float2 in_ = make_float2(a.x + b.x, a.y + b.y);
                        a = *(const float2*)(g0 + 80 + jp); b = *(const float2*)(g1 + 80 + jp);
                        float2 hn = make_float2(a.x + b.x, a.y + b.y);
                        float2 br = *(const float2*)(C.cb1 + jp);
                        float2 bz = *(const float2*)(C.cb1 + 40 + jp);
                        float2 bi = *(const float2*)(C.bi1n + jp);
                        float2 bhn = *(const float2*)(C.bh1n + jp);
                        float2 h  = *(float2*)&S.h1[row][jp];
                        float r0 = sigm(ir.x + hr.x + br.x);
                        float r1 = sigm(ir.y + hr.y + br.y);
                        float z0 = sigm(iz.x + hz.x + bz.x);
                        float z1 = sigm(iz.y + hz.y + bz.y);
                        float n0 = tanh_f(fmaf(r0, hn.x + bhn.x, in_.x + bi.x));
                        float n1 = tanh_f(fmaf(r1, hn.y + bhn.y, in_.y + bi.y));
                        h.x = fmaf(z0, h.x - n0, n0);
                        h.y = fmaf(z1, h.y - n1, n1);
                        *(float2*)&S.h1[row][jp] = h;
                    }
                }
            }
        }
        slot_bar(slot);
    }

    // ---- write final layer-1 hidden state (clamped rows dup, benign) ----
    for (int e = r; e < NR * HSZ; e += SLOT_T) {
        int row = e / HSZ, jj = e % HSZ;
        int grow = base + row; if (grow > NB - 1) grow = NB - 1;
        out[grow * HSZ + jj] = S.h1[row][jj];
    }
}

extern "C" void kernel_launch(void* const* d_in, const int* in_sizes, int n_in,
                              void* d_out, int out_size) {
    const float* x    = (const float*)d_in[0];
    const float* Wih0 = (const float*)d_in[1];
    const float* Whh0 = (const float*)d_in[2];
    const float* bih0 = (const float*)d_in[3];
    const float* bhh0 = (const float*)d_in[4];
    const float* Wih1 = (const float*)d_in[5];
    const float* Whh1 = (const float*)d_in[6];
    const float* bih1 = (const float*)d_in[7];
    const float* bhh1 = (const float*)d_in[8];
    float* out = (float*)d_out;

    xg_prepass<<<NB, 128>>>(x, Wih0, bih0);

    const int smem_bytes = (int)sizeof(CTAS);
    cudaFuncSetAttribute(gru_main,
                         cudaFuncAttributeMaxDynamicSharedMemorySize, smem_bytes);
    gru_main<<<148, CTA_T, smem_bytes>>>(Whh0, bhh0, Wih1, Whh1, bih1, bhh1, out);
}

// round 14
// speedup vs baseline: 1.1609x; 1.1609x over previous
#include <cuda_runtime.h>

// GRUExtractor: 2-layer GRU, B=4096, T=256, I=16, H=40, fp32.
// R14: R12 skeleton (U=2, 768-thr CTA, xg prepass) +
//      (a) biases folded into Phase-A partials (half-0 threads add them),
//      (b) Phase B vectorized float2 (560 tasks, no bias loads).

#define HSZ 40
#define ISZ 16
#define TSZ 256
#define NB  4096
#define NR  14
#define SLOT_T 384
#define CTA_T  768
#define NGR 120

typedef unsigned long long u64;
typedef ulonglong2 u64x2;

__device__ float g_xg[(size_t)NB * TSZ * NGR];   // xg[b][t][gate_row] (incl bih0)

__device__ __forceinline__ void upk2(u64 d, float& a, float& b) {
    asm("mov.b64 {%0,%1},%2;" : "=f"(a), "=f"(b) : "l"(d));
}
__device__ __forceinline__ u64 ffma2(u64 a, u64 b, u64 c) {
    u64 d; asm("fma.rn.f32x2 %0,%1,%2,%3;" : "=l"(d) : "l"(a), "l"(b), "l"(c)); return d;
}
__device__ __forceinline__ u64 add2(u64 a, u64 b) {
    u64 d; asm("add.rn.f32x2 %0,%1,%2;" : "=l"(d) : "l"(a), "l"(b)); return d;
}
__device__ __forceinline__ float hsum2(u64 d) { float a, b; upk2(d, a, b); return a + b; }

__device__ __forceinline__ float sigm(float x) {
    return __fdividef(1.0f, 1.0f + __expf(-x));
}
__device__ __forceinline__ float tanh_f(float x) {
    return __fdividef(2.0f, 1.0f + __expf(-2.0f * x)) - 1.0f;
}

__device__ __forceinline__ void slot_bar(int slot) {
    asm volatile("bar.sync %0, %1;" :: "r"(slot + 1), "r"(SLOT_T) : "memory");
}

// ---------------- prepass: xg = Wih0 . x + bih0 ----------------
__global__ void __launch_bounds__(128, 8) xg_prepass(
    const float* __restrict__ x, const float* __restrict__ Wih0,
    const float* __restrict__ bih0)
{
    __shared__ __align__(16) float4 xs[TSZ * 4];
    const int b = blockIdx.x;
    const int tid = threadIdx.x;
    for (int i = tid; i < TSZ * 4; i += 128)
        xs[i] = ((const float4*)x)[b * (TSZ * 4) + i];
    u64 w[8]; float bias = 0.0f;
    const int gr = tid;
    if (gr < NGR) {
        const u64x2* wp = (const u64x2*)(Wih0 + gr * ISZ);
        #pragma unroll
        for (int q = 0; q < 4; q++) { u64x2 v = wp[q]; w[2*q] = v.x; w[2*q+1] = v.y; }
        bias = bih0[gr];
    }
    __syncthreads();
    if (gr < NGR) {
        float* dst = g_xg + (size_t)b * TSZ * NGR + gr;
        #pragma unroll 4
        for (int t = 0; t < TSZ; t++) {
            const u64x2* xp = (const u64x2*)&xs[t * 4];
            u64 a0 = 0ull, a1 = 0ull;
            #pragma unroll
            for (int q = 0; q < 4; q++) {
                u64x2 v = xp[q];
                a0 = ffma2(w[2*q],   v.x, a0);
                a1 = ffma2(w[2*q+1], v.y, a1);
            }
            dst[t * NGR] = hsum2(add2(a0, a1)) + bias;
        }
    }
}

// ---------------- main recurrent kernel ----------------
struct Slot {
    float h0[NR][HSZ];
    float h1[NR][HSZ];
    float pA[2][NR][NGR];         // L0 partials [half] (half0 incl bhh0)
    float pB[2][2][NR][NGR];      // L1 partials [mat][half] (half0 incl bias)
    float xb[2][NR][NGR];         // xg double buffer
};

__global__ void __launch_bounds__(CTA_T, 1) gru_main(
    const float* __restrict__ Whh0,
    const float* __restrict__ bhh0,
    const float* __restrict__ Wih1,
    const float* __restrict__ Whh1,
    const float* __restrict__ bih1,
    const float* __restrict__ bhh1,
    float* __restrict__ out)
{
    extern __shared__ __align__(16) char smraw[];
    Slot* sl = (Slot*)smraw;

    const int tid  = threadIdx.x;
    const int slot = tid / SLOT_T;
    const int r    = tid - slot * SLOT_T;
    Slot& S = sl[slot];
    const int base = (blockIdx.x * 2 + slot) * NR;

    // ---- roles: r<128 -> L0 (warp-uniform half); 128..383 -> L1 ----
    const bool isL0 = (r < 128);
    int half, mat = 0, gr0;
    const float* Wsrc;
    const float* Bsrc;
    if (isL0) {
        half = r >> 6;                       // warps 0-1: half0, warps 2-3: half1
        int m = r & 63; if (m > 59) m = 59;  // dup lanes clamp (benign)
        gr0 = 2 * m;
        Wsrc = Whh0;
        Bsrc = bhh0;
    } else {
        int i2 = r - 128;
        half = i2 >> 7;                      // warp-uniform
        mat  = (i2 >> 6) & 1;                // warp-uniform: 0=Wih1(.h0) 1=Whh1(.h1)
        int u = i2 & 63; if (u > 59) u = 59;
        gr0 = 2 * u;
        Wsrc = mat ? Whh1 : Wih1;
        Bsrc = mat ? bhh1 : bih1;
    }
    const int hofs = half * 20;

    // ---- register weights: 2 gate-rows x half-k = 20 u64; bias folded @half0 ----
    u64 w[20];
    float2 breg = make_float2(0.0f, 0.0f);
    {
        const u64x2* p0 = (const u64x2*)(Wsrc + gr0 * HSZ + hofs);
        const u64x2* p1 = (const u64x2*)(Wsrc + (gr0 + 1) * HSZ + hofs);
        #pragma unroll
        for (int q = 0; q < 5; q++) {
            u64x2 v0 = p0[q]; w[2*q]      = v0.x; w[2*q+1]      = v0.y;
            u64x2 v1 = p1[q]; w[10 + 2*q] = v1.x; w[10 + 2*q+1] = v1.y;
        }
        if (half == 0) breg = make_float2(Bsrc[gr0], Bsrc[gr0 + 1]);
    }

    // ---- init: zero h, stage xg(t=0) ----
    for (int e = r; e < NR * HSZ; e += SLOT_T) {
        S.h0[e / HSZ][e % HSZ] = 0.0f;
        S.h1[e / HSZ][e % HSZ] = 0.0f;
    }
    for (int idx = r; idx < NR * 30; idx += SLOT_T) {
        int row = idx / 30, c = idx - row * 30;
        int grow = base + row; if (grow > NB - 1) grow = NB - 1;
        ((float4*)S.xb[0][row])[c] =
            ((const float4*)g_xg)[((size_t)grow * TSZ) * 30 + c];
    }
    __syncthreads();

    // ---- supersteps: L0 computes t=s, L1 computes t=s-1 ----
    for (int s = 0; s <= TSZ; ++s) {
        // register prefetch of xg(s+1)
        float4 pf0, pf1;
        int pi0 = -1, pi1 = -1;
        const int s1 = s + 1;
        if (s1 < TSZ) {
            if (r < NR * 30) {
                int row = r / 30, c = r - row * 30;
                int grow = base + row; if (grow > NB - 1) grow = NB - 1;
                pf0 = ((const float4*)g_xg)[((size_t)grow * TSZ + s1) * 30 + c];
                pi0 = r;
            }
            int idx = r + SLOT_T;
            if (idx < NR * 30) {
                int row = idx / 30, c = idx - row * 30;
                int grow = base + row; if (grow > NB - 1) grow = NB - 1;
                pf1 = ((const float4*)g_xg)[((size_t)grow * TSZ + s1) * 30 + c];
                pi1 = idx;
            }
        }

        // ===== PHASE A: partial h-dots (bias pre-folded at half0) =====
        const bool act = isL0 ? (s < TSZ) : (s >= 1);
        if (act) {
            const float (*hsrc)[HSZ] = (isL0 || mat == 0) ? S.h0 : S.h1;
            float* pout = isL0 ? &S.pA[half][0][0] : &S.pB[mat][half][0][0];
            #pragma unroll 2
            for (int row = 0; row < NR; ++row) {
                const u64x2* hp = (const u64x2*)(&hsrc[row][hofs]);
                u64 a0 = 0ull, a1 = 0ull, b0 = 0ull, b1 = 0ull;
                #pragma unroll
                for (int q = 0; q < 5; q++) {
                    u64x2 v = hp[q];
                    a0 = ffma2(w[2*q],        v.x, a0);
                    a1 = ffma2(w[2*q+1],      v.y, a1);
                    b0 = ffma2(w[10 + 2*q],   v.x, b0);
                    b1 = ffma2(w[10 + 2*q+1], v.y, b1);
                }
                float2 pr;
                pr.x = hsum2(add2(a0, a1)) + breg.x;
                pr.y = hsum2(add2(b0, b1)) + breg.y;
                *(float2*)&pout[row * NGR + gr0] = pr;
            }
        }

        // commit xg prefetch to other parity
        if (pi0 >= 0) ((float4*)&S.xb[s1 & 1][0][0])[pi0] = pf0;
        if (pi1 >= 0) ((float4*)&S.xb[s1 & 1][0][0])[pi1] = pf1;
        slot_bar(slot);

        // ===== PHASE B: combine + activations + h update, float2 (560 tasks) =====
        #pragma unroll
        for (int k = 0; k < 2; k++) {
            int t = r + SLOT_T * k;
            if (t < 2 * NR * 20) {
                int lay = t / (NR * 20);
                int rem = t - lay * (NR * 20);
                int row = rem / 20;
                int jp  = (rem - row * 20) * 2;
                if (lay == 0) {
                    if (s < TSZ) {
                        const float* q0 = S.pA[0][row];
                        const float* q1 = S.pA[1][row];
                        const float* xv = S.xb[s & 1][row];
                        float2 a, b;
                        a = *(const float2*)(q0 + jp);      b = *(const float2*)(q1 + jp);
                        float2 hr = make_float2(a.x + b.x, a.y + b.y);
                        a = *(const float2*)(q0 + 40 + jp); b = *(const float2*)(q1 + 40 + jp);
                        float2 hz = make_float2(a.x + b.x, a.y + b.y);
                        a = *(const float2*)(q0 + 80 + jp); b = *(const float2*)(q1 + 80 + jp);
                        float2 hn = make_float2(a.x + b.x, a.y + b.y);
                        float2 xr = *(const float2*)(xv + jp);
                        float2 xz = *(const float2*)(xv + 40 + jp);
                        float2 xn = *(const float2*)(xv + 80 + jp);
                        float2 h  = *(float2*)&S.h0[row][jp];
                        float r0 = sigm(xr.x + hr.x);
                        float r1 = sigm(xr.y + hr.y);
                        float z0 = sigm(xz.x + hz.x);
                        float z1 = sigm(xz.y + hz.y);
                        float n0 = tanh_f(fmaf(r0, hn.x, xn.x));
                        float n1 = tanh_f(fmaf(r1, hn.y, xn.y));
                        h.x = fmaf(z0, h.x - n0, n0);
                        h.y = fmaf(z1, h.y - n1, n1);
                        *(float2*)&S.h0[row][jp] = h;
                    }
                } else {
                    if (s >= 1) {
                        const float* i0 = S.pB[0][0][row];
                        const float* i1 = S.pB[0][1][row];
                        const float* g0 = S.pB[1][0][row];
                        const float* g1 = S.pB[1][1][row];
                        float2 a, b;
                        a = *(const float2*)(i0 + jp);      b = *(const float2*)(i1 + jp);
                        float2 ir = make_float2(a.x + b.x, a.y + b.y);
                        a = *(const float2*)(g0 + jp);      b = *(const float2*)(g1 + jp);
                        float2 hr = make_float2(a.x + b.x, a.y + b.y);
                        a = *(const float2*)(i0 + 40 + jp); b = *(const float2*)(i1 + 40 + jp);
                        float2 iz = make_float2(a.x + b.x, a.y + b.y);
                        a = *(const float2*)(g0 + 40 + jp); b = *(const float2*)(g1 + 40 + jp);
                        float2 hz = make_float2(a.x + b.x, a.y + b.y);
                        a = *(const float2*)(i0 + 80 + jp); b = *(const float2*)(i1 + 80 + jp);
                        float2 in_ = make_float2(a.x + b.x, a.y + b.y);
                        a = *(const float2*)(g0 + 80 + jp); b = *(const float2*)(g1 + 80 + jp);
                        float2 hn = make_float2(a.x + b.x, a.y + b.y);
                        float2 h  = *(float2*)&S.h1[row][jp];
                        float r0 = sigm(ir.x + hr.x);
                        float r1 = sigm(ir.y + hr.y);
                        float z0 = sigm(iz.x + hz.x);
                        float z1 = sigm(iz.y + hz.y);
                        float n0 = tanh_f(fmaf(r0, hn.x, in_.x));
                        float n1 = tanh_f(fmaf(r1, hn.y, in_.y));
                        h.x = fmaf(z0, h.x - n0, n0);
                        h.y = fmaf(z1, h.y - n1, n1);
                        *(float2*)&S.h1[row][jp] = h;
                    }
                }
            }
        }
        slot_bar(slot);
    }

    // ---- write final layer-1 hidden state (clamped rows dup, benign) ----
    for (int e = r; e < NR * HSZ; e += SLOT_T) {
        int row = e / HSZ, jj = e % HSZ;
        int grow = base + row; if (grow > NB - 1) grow = NB - 1;
        out[grow * HSZ + jj] = S.h1[row][jj];
    }
}

extern "C" void kernel_launch(void* const* d_in, const int* in_sizes, int n_in,
                              void* d_out, int out_size) {
    const float* x    = (const float*)d_in[0];
    const float* Wih0 = (const float*)d_in[1];
    const float* Whh0 = (const float*)d_in[2];
    const float* bih0 = (const float*)d_in[3];
    const float* bhh0 = (const float*)d_in[4];
    const float* Wih1 = (const float*)d_in[5];
    const float* Whh1 = (const float*)d_in[6];
    const float* bih1 = (const float*)d_in[7];
    const float* bhh1 = (const float*)d_in[8];
    float* out = (float*)d_out;

    xg_prepass<<<NB, 128>>>(x, Wih0, bih0);

    const int smem_bytes = 2 * (int)sizeof(Slot);
    cudaFuncSetAttribute(gru_main,
                         cudaFuncAttributeMaxDynamicSharedMemorySize, smem_bytes);
    gru_main<<<148, CTA_T, smem_bytes>>>(Whh0, bhh0, Wih1, Whh1, bih1, bhh1, out);
}